// round 3
// baseline (speedup 1.0000x reference)
#include <cuda_runtime.h>

#define NW  17
#define PAD 20
#define TPB 128

// Overflow/underflow-safe fast tanh: 1 - 2/(1 + 2^(2*log2(e)*x))
//  x -> +inf : e=inf, rcp(inf)=0 -> 1
//  x -> -inf : e=0   -> 1-2 = -1
__device__ __forceinline__ float ex2_approx(float x) {
    float y; asm("ex2.approx.f32 %0, %1;" : "=f"(y) : "f"(x)); return y;
}
__device__ __forceinline__ float rcp_approx(float x) {
    float y; asm("rcp.approx.f32 %0, %1;" : "=f"(y) : "f"(x)); return y;
}
__device__ __forceinline__ float fast_tanh(float x) {
    float e = ex2_approx(x * 2.8853900817779268f);   // 2*log2(e)
    return fmaf(-2.0f, rcp_approx(e + 1.0f), 1.0f);
}

// acc[j] (+)= sum_k v[k] * W[k][j]   -- W rows 16B aligned, loaded as float4
template <bool INIT>
__device__ __forceinline__ void matvec(float acc[NW], const float v[NW],
                                       const float W[NW][PAD]) {
#pragma unroll
    for (int k = 0; k < NW; ++k) {
        const float vk = v[k];
        const float4* w4 = reinterpret_cast<const float4*>(W[k]);
#pragma unroll
        for (int q = 0; q < 4; ++q) {
            float4 w = w4[q];
            if (INIT && k == 0) {
                acc[4*q+0] = vk * w.x;
                acc[4*q+1] = vk * w.y;
                acc[4*q+2] = vk * w.z;
                acc[4*q+3] = vk * w.w;
            } else {
                acc[4*q+0] = fmaf(vk, w.x, acc[4*q+0]);
                acc[4*q+1] = fmaf(vk, w.y, acc[4*q+1]);
                acc[4*q+2] = fmaf(vk, w.z, acc[4*q+2]);
                acc[4*q+3] = fmaf(vk, w.w, acc[4*q+3]);
            }
        }
        if (INIT && k == 0) acc[16] = vk * W[k][16];
        else                acc[16] = fmaf(vk, W[k][16], acc[16]);
    }
}

// v[j] = tanh(s * Wf[j] + bf[j])
__device__ __forceinline__ void feat(float v[NW], float s,
                                     const float* sWf, const float* sbf) {
#pragma unroll
    for (int j = 0; j < NW; ++j) v[j] = fast_tanh(fmaf(s, sWf[j], sbf[j]));
}

// m[j] = tanh(P[j] + Q[j] + bm[j])
__device__ __forceinline__ void mkmsg(float m[NW], const float P[NW],
                                      const float Q[NW], const float* sbm) {
#pragma unroll
    for (int j = 0; j < NW; ++j) m[j] = fast_tanh(P[j] + Q[j] + sbm[j]);
}

extern "C" __global__ void __launch_bounds__(TPB)
mp_kernel(const float* __restrict__ inp,
          const float* __restrict__ Wf,  const float* __restrict__ bf,
          const float* __restrict__ Wm,  const float* __restrict__ bm,
          const float* __restrict__ Wu,  const float* __restrict__ bu,
          const float* __restrict__ Wr,  const float* __restrict__ br,
          float* __restrict__ out, int B)
{
    __shared__ __align__(16) float sM1[NW][PAD];   // Wm[:17]
    __shared__ __align__(16) float sM2[NW][PAD];   // Wm[17:34]
    __shared__ __align__(16) float sU1[NW][PAD];   // Wu[:17]
    __shared__ __align__(16) float sU2[NW][PAD];   // Wu[17:34]
    __shared__ __align__(16) float sU34[NW][PAD];  // Wu[34:51] + Wu[51:68]
    __shared__ float sWf[NW], sbf[NW], sbm[NW], sbu[NW], sWr[5 * NW], sbr;

    for (int idx = threadIdx.x; idx < NW * NW; idx += TPB) {
        int k = idx / NW, j = idx % NW;
        sM1[k][j]  = Wm[idx];
        sM2[k][j]  = Wm[NW * NW + idx];
        sU1[k][j]  = Wu[idx];
        sU2[k][j]  = Wu[NW * NW + idx];
        sU34[k][j] = Wu[2 * NW * NW + idx] + Wu[3 * NW * NW + idx];
    }
    if (threadIdx.x < NW) {
        sWf[threadIdx.x] = Wf[threadIdx.x];
        sbf[threadIdx.x] = bf[threadIdx.x];
        sbm[threadIdx.x] = bm[threadIdx.x];
        sbu[threadIdx.x] = bu[threadIdx.x];
    }
    for (int idx = threadIdx.x; idx < 5 * NW; idx += TPB) sWr[idx] = Wr[idx];
    if (threadIdx.x == 0) sbr = br[0];
    __syncthreads();

    const int row = blockIdx.x * TPB + threadIdx.x;
    if (row >= B) return;

    const float x0 = inp[row * 5 + 0];
    const float x1 = inp[row * 5 + 1];
    const float x2 = inp[row * 5 + 2];
    const float x3 = inp[row * 5 + 3];
    const float x4 = inp[row * 5 + 4];

    float v[NW], m[NW];
    float Pa[NW], Qa[NW];          // node a: live until edge d-a
    float P0[NW], Q0[NW];          // rolling slot (b, then d)
    float P1[NW], Q1[NW];          // rolling slot (c)
    float accA[NW], accB[NW], accC[NW], accD[NW];

    // ---- node a ----
    feat(v, x0, sWf, sbf);
    matvec<true>(Pa, v, sM1);
    matvec<true>(Qa, v, sM2);
#pragma unroll
    for (int j = 0; j < NW; ++j) accA[j] = sbu[j];
    matvec<false>(accA, v, sU34);

    // ---- node b (P0/Q0) ----
    feat(v, x1, sWf, sbf);
    matvec<true>(P0, v, sM1);
    matvec<true>(Q0, v, sM2);
#pragma unroll
    for (int j = 0; j < NW; ++j) accB[j] = sbu[j];
    matvec<false>(accB, v, sU34);

    // edge a-b
    mkmsg(m, Pa, Q0, sbm); matvec<false>(accA, m, sU1);   // Mab -> m1 of A
    mkmsg(m, P0, Qa, sbm); matvec<false>(accB, m, sU1);   // Mba -> m1 of B

    // ---- node c (P1/Q1) ----
    feat(v, x2, sWf, sbf);
    matvec<true>(P1, v, sM1);
    matvec<true>(Q1, v, sM2);
#pragma unroll
    for (int j = 0; j < NW; ++j) accC[j] = sbu[j];
    matvec<false>(accC, v, sU34);

    // edge b-c
    mkmsg(m, P0, Q1, sbm); matvec<false>(accB, m, sU2);   // Mbc -> m2 of B
    mkmsg(m, P1, Q0, sbm); matvec<false>(accC, m, sU1);   // Mcb -> m1 of C
    // P0/Q0 (node b) now dead -> reuse for node d

    // ---- node d (P0/Q0 reused) ----
    feat(v, x3, sWf, sbf);
    matvec<true>(P0, v, sM1);
    matvec<true>(Q0, v, sM2);
#pragma unroll
    for (int j = 0; j < NW; ++j) accD[j] = sbu[j];
    matvec<false>(accD, v, sU34);

    // edge c-d
    mkmsg(m, P1, Q0, sbm); matvec<false>(accC, m, sU2);   // Mcd -> m2 of C
    mkmsg(m, P0, Q1, sbm); matvec<false>(accD, m, sU1);   // Mdc -> m1 of D

    // edge d-a
    mkmsg(m, P0, Qa, sbm); matvec<false>(accD, m, sU2);   // Mda -> m2 of D
    mkmsg(m, Pa, Q0, sbm); matvec<false>(accA, m, sU2);   // Mad -> m2 of A

    // ---- readout for a..d ----
    float o = sbr;
#pragma unroll
    for (int j = 0; j < NW; ++j) o = fmaf(fast_tanh(accA[j]), sWr[j],          o);
#pragma unroll
    for (int j = 0; j < NW; ++j) o = fmaf(fast_tanh(accB[j]), sWr[NW + j],     o);
#pragma unroll
    for (int j = 0; j < NW; ++j) o = fmaf(fast_tanh(accC[j]), sWr[2 * NW + j], o);
#pragma unroll
    for (int j = 0; j < NW; ++j) o = fmaf(fast_tanh(accD[j]), sWr[3 * NW + j], o);

    // ---- node e (reuse accA): Ue = tanh(e@U34 + bu) ----
    feat(v, x4, sWf, sbf);
#pragma unroll
    for (int j = 0; j < NW; ++j) accA[j] = sbu[j];
    matvec<false>(accA, v, sU34);
#pragma unroll
    for (int j = 0; j < NW; ++j) o = fmaf(fast_tanh(accA[j]), sWr[4 * NW + j], o);

    out[row] = o;
}

extern "C" void kernel_launch(void* const* d_in, const int* in_sizes, int n_in,
                              void* d_out, int out_size)
{
    const float* inp = (const float*)d_in[0];
    const float* Wf  = (const float*)d_in[1];
    const float* bf  = (const float*)d_in[2];
    const float* Wm  = (const float*)d_in[3];
    const float* bm  = (const float*)d_in[4];
    const float* Wu  = (const float*)d_in[5];
    const float* bu  = (const float*)d_in[6];
    const float* Wr  = (const float*)d_in[7];
    const float* br  = (const float*)d_in[8];
    float* out = (float*)d_out;

    const int B = in_sizes[0] / 5;
    const int grid = (B + TPB - 1) / TPB;
    mp_kernel<<<grid, TPB>>>(inp, Wf, bf, Wm, bm, Wu, bu, Wr, br, out, B);
}